// round 1
// baseline (speedup 1.0000x reference)
#include <cuda_runtime.h>
#include <cuda_bf16.h>

// SplineActivation: y[b][d] = sum_k Bspline_k(x[b][d]) * coeffs[d][k]
// Uniform cubic B-spline on knots -2.5:0.5:2.5 -> closed-form cardinal basis.
// Thread layout: each thread owns 4 consecutive dims (one float4 column group),
// caches its 28 spline coefficients in registers, and streams ROWS_PER batch
// rows. x/out accesses are fully coalesced float4; coeffs read once per thread.

#define INPUT_DIM 4096
#define BATCH_N   4096
#define ROWS_PER  16
#define TPB       128

__device__ __forceinline__ float spline_eval(float xv, const float* __restrict__ c) {
    // t = (x + 1) * 2  in [0, 4); interval j, local param u in [0,1)
    float t = fmaf(xv, 2.0f, 2.0f);
    int j = (int)t;
    j = j < 0 ? 0 : (j > 3 ? 3 : j);
    float u = t - (float)j;

    float om  = 1.0f - u;
    float u2  = u * u;
    float u3  = u2 * u;
    float om3 = om * om * om;

    const float k6 = 1.0f / 6.0f;
    float b0 = om3 * k6;                                            // (1-u)^3 / 6
    float b1 = fmaf(3.0f, u3, fmaf(-6.0f, u2, 4.0f)) * k6;          // (3u^3-6u^2+4)/6
    float b2 = fmaf(-3.0f, u3, fmaf(3.0f, u2, fmaf(3.0f, u, 1.0f))) * k6; // (-3u^3+3u^2+3u+1)/6
    float b3 = u3 * k6;                                             // u^3 / 6

    // Static shift network selecting the window c[j..j+3] (no dynamic reg indexing).
    bool hi = (j >= 2);
    float d0 = hi ? c[2] : c[0];
    float d1 = hi ? c[3] : c[1];
    float d2 = hi ? c[4] : c[2];
    float d3 = hi ? c[5] : c[3];
    float d4 = hi ? c[6] : c[4];
    bool odd = (j & 1) != 0;
    float e0 = odd ? d1 : d0;
    float e1 = odd ? d2 : d1;
    float e2 = odd ? d3 : d2;
    float e3 = odd ? d4 : d3;

    return fmaf(b0, e0, fmaf(b1, e1, fmaf(b2, e2, b3 * e3)));
}

__global__ void __launch_bounds__(TPB)
spline_activation_kernel(const float4* __restrict__ x,
                         const float*  __restrict__ coeffs,
                         float4* __restrict__ out) {
    const int DQ = INPUT_DIM / 4;                       // 1024 float4 columns
    int dq = blockIdx.x * TPB + threadIdx.x;            // column-quad index
    int d0 = dq * 4;

    // Cache 7 coefficients for each of the 4 owned dims in registers.
    float c[28];
#pragma unroll
    for (int i = 0; i < 28; ++i)
        c[i] = __ldg(coeffs + (size_t)d0 * 7 + i);

    int brow0 = blockIdx.y * ROWS_PER;

#pragma unroll 4
    for (int r = 0; r < ROWS_PER; ++r) {
        int b = brow0 + r;
        size_t idx = (size_t)b * DQ + dq;
        float4 xv = __ldg(x + idx);
        float4 ov;
        ov.x = spline_eval(xv.x, c + 0);
        ov.y = spline_eval(xv.y, c + 7);
        ov.z = spline_eval(xv.z, c + 14);
        ov.w = spline_eval(xv.w, c + 21);
        out[idx] = ov;
    }
}

extern "C" void kernel_launch(void* const* d_in, const int* in_sizes, int n_in,
                              void* d_out, int out_size) {
    const float4* x      = (const float4*)d_in[0];   // (4096, 4096) fp32
    const float*  coeffs = (const float*)d_in[1];    // (4096, 7) fp32
    float4*       out    = (float4*)d_out;           // (4096, 4096) fp32

    dim3 grid((INPUT_DIM / 4) / TPB, BATCH_N / ROWS_PER, 1);  // (8, 256)
    spline_activation_kernel<<<grid, TPB>>>(x, coeffs, out);
}

// round 2
// speedup vs baseline: 1.2002x; 1.2002x over previous
#include <cuda_runtime.h>
#include <cuda_bf16.h>

// SplineActivation: y[b][d] = sum_k Bspline_k(x[b][d]) * coeffs[d][k]
// Uniform cubic B-spline, closed-form cardinal basis collapsed into a single
// Horner cubic per element:
//   y = ((A u + B) u + C) u + D,   u = frac(t),  t = 2x+2 in [0,4)
//   A = -e0+3e1-3e2+e3, B = 3e0-6e1+3e2, C = 3(e2-e0), D = e0+4e1+e2
// with e = coeffs[d][j..j+3] (pre-scaled by 1/6) selected by a 2-level
// static shift network (no dynamic register indexing, no clamps needed
// since x in [-1,1) by construction).

#define INPUT_DIM 4096
#define BATCH_N   4096
#define ROWS_PER  8
#define TPB       128

__device__ __forceinline__ float spline_eval(float xv, const float* __restrict__ c) {
    float t = fmaf(xv, 2.0f, 2.0f);   // [0, 4)
    int j = (int)t;                    // 0..3 guaranteed
    float u = t - (float)j;

    bool hi  = (j >= 2);
    bool odd = (j & 1) != 0;

    // 2-level shift network: window c[j..j+3]
    float d0 = hi ? c[2] : c[0];
    float d1 = hi ? c[3] : c[1];
    float d2 = hi ? c[4] : c[2];
    float d3 = hi ? c[5] : c[3];
    float d4 = hi ? c[6] : c[4];
    float e0 = odd ? d1 : d0;
    float e1 = odd ? d2 : d1;
    float e2 = odd ? d3 : d2;
    float e3 = odd ? d4 : d3;

    // Horner coefficients (c already scaled by 1/6)
    float s1 = e1 - e2;
    float tA = e3 - e0;
    float A  = fmaf(3.0f, s1, tA);
    float s2 = e0 + e2;
    float B  = fmaf(-6.0f, e1, 3.0f * s2);
    float C  = 3.0f * (e2 - e0);
    float D  = fmaf(4.0f, e1, s2);

    return fmaf(fmaf(fmaf(A, u, B), u, C), u, D);
}

__global__ void __launch_bounds__(TPB)
spline_activation_kernel(const float4* __restrict__ x,
                         const float4* __restrict__ coeffs4,
                         float4* __restrict__ out) {
    const int DQ = INPUT_DIM / 4;                       // 1024 float4 columns
    int dq = blockIdx.x * TPB + threadIdx.x;            // column-quad index

    // 28 coefficients (4 dims x 7), 16B-aligned since 4*7*dq floats = 112*dq B.
    // Pre-scale by 1/6 so the Horner result is final.
    const float k6 = 1.0f / 6.0f;
    float c[28];
    const float4* cp = coeffs4 + (size_t)dq * 7;
#pragma unroll
    for (int i = 0; i < 7; ++i) {
        float4 v = __ldg(cp + i);
        c[4 * i + 0] = v.x * k6;
        c[4 * i + 1] = v.y * k6;
        c[4 * i + 2] = v.z * k6;
        c[4 * i + 3] = v.w * k6;
    }

    int brow0 = blockIdx.y * ROWS_PER;

#pragma unroll
    for (int r = 0; r < ROWS_PER; ++r) {
        size_t idx = (size_t)(brow0 + r) * DQ + dq;
        float4 xv = __ldg(x + idx);
        float4 ov;
        ov.x = spline_eval(xv.x, c + 0);
        ov.y = spline_eval(xv.y, c + 7);
        ov.z = spline_eval(xv.z, c + 14);
        ov.w = spline_eval(xv.w, c + 21);
        out[idx] = ov;
    }
}

extern "C" void kernel_launch(void* const* d_in, const int* in_sizes, int n_in,
                              void* d_out, int out_size) {
    const float4* x      = (const float4*)d_in[0];   // (4096, 4096) fp32
    const float4* coeffs = (const float4*)d_in[1];   // (4096, 7) fp32
    float4*       out    = (float4*)d_out;           // (4096, 4096) fp32

    dim3 grid((INPUT_DIM / 4) / TPB, BATCH_N / ROWS_PER, 1);  // (8, 512)
    spline_activation_kernel<<<grid, TPB>>>(x, coeffs, out);
}